// round 1
// baseline (speedup 1.0000x reference)
#include <cuda_runtime.h>

#define DM     2048
#define NH     16
#define HD     128
#define BATCH  4
#define TQL    1024
#define CL     1024
#define MROWS  (BATCH*TQL)                  // 4096
#define OFF_K  ((size_t)BATCH*TQL*DM)       // 8388608
#define OFF_V  (OFF_K + (size_t)BATCH*NH*2048*HD)  // 25165824

__device__ float g_Q[BATCH*TQL*DM];
__device__ float g_ctx[BATCH*TQL*DM];

// ---------------------------------------------------------------------------
// SGEMM: C[M=4096, N=2048] = A[4096,2048] @ W[2048,2048]^T + bias
// mode 0: row-major C[m][n]
// mode 1: kv-cache layout: n -> (h=bn, dh), m -> (b, t); write at
//         C[((b*16+h)*2048 + 1024 + t)*128 + dh]
// ---------------------------------------------------------------------------
__global__ __launch_bounds__(256) void sgemm_bias(
    const float* __restrict__ A, const float* __restrict__ W,
    const float* __restrict__ bias, float* __restrict__ C, int mode)
{
    __shared__ float As[16][128];
    __shared__ float Ws[16][128];
    const int tid = threadIdx.x;
    const int bn = blockIdx.x, bm = blockIdx.y;
    const int ty = tid >> 4, tx = tid & 15;
    const int rowA0 = bm * 128, rowW0 = bn * 128;

    float acc[8][8];
#pragma unroll
    for (int i = 0; i < 8; i++)
#pragma unroll
        for (int j = 0; j < 8; j++) acc[i][j] = 0.f;

    for (int k0 = 0; k0 < DM; k0 += 16) {
#pragma unroll
        for (int i = 0; i < 2; i++) {
            int l = tid * 2 + i;
            int r = l >> 2, kg = (l & 3) * 4;
            float4 a = *(const float4*)(A + (size_t)(rowA0 + r) * DM + k0 + kg);
            As[kg + 0][r] = a.x; As[kg + 1][r] = a.y;
            As[kg + 2][r] = a.z; As[kg + 3][r] = a.w;
            float4 w = *(const float4*)(W + (size_t)(rowW0 + r) * DM + k0 + kg);
            Ws[kg + 0][r] = w.x; Ws[kg + 1][r] = w.y;
            Ws[kg + 2][r] = w.z; Ws[kg + 3][r] = w.w;
        }
        __syncthreads();
#pragma unroll
        for (int kk = 0; kk < 16; kk++) {
            float av[8], wv[8];
            *(float4*)(av)     = *(const float4*)&As[kk][ty * 8];
            *(float4*)(av + 4) = *(const float4*)&As[kk][ty * 8 + 4];
            *(float4*)(wv)     = *(const float4*)&Ws[kk][tx * 8];
            *(float4*)(wv + 4) = *(const float4*)&Ws[kk][tx * 8 + 4];
#pragma unroll
            for (int i = 0; i < 8; i++)
#pragma unroll
                for (int j = 0; j < 8; j++)
                    acc[i][j] += av[i] * wv[j];
        }
        __syncthreads();
    }

    float bv[8];
#pragma unroll
    for (int j = 0; j < 8; j++) bv[j] = bias[rowW0 + tx * 8 + j];

    if (mode == 0) {
#pragma unroll
        for (int i = 0; i < 8; i++) {
            int m = rowA0 + ty * 8 + i;
            float4 v0, v1;
            v0.x = acc[i][0] + bv[0]; v0.y = acc[i][1] + bv[1];
            v0.z = acc[i][2] + bv[2]; v0.w = acc[i][3] + bv[3];
            v1.x = acc[i][4] + bv[4]; v1.y = acc[i][5] + bv[5];
            v1.z = acc[i][6] + bv[6]; v1.w = acc[i][7] + bv[7];
            *(float4*)(C + (size_t)m * DM + rowW0 + tx * 8)     = v0;
            *(float4*)(C + (size_t)m * DM + rowW0 + tx * 8 + 4) = v1;
        }
    } else {
#pragma unroll
        for (int i = 0; i < 8; i++) {
            int m = rowA0 + ty * 8 + i;
            int b = m >> 10, t = m & 1023;
            size_t base = (((size_t)(b * NH + bn) * 2048) + CL + t) * HD + tx * 8;
            float4 v0, v1;
            v0.x = acc[i][0] + bv[0]; v0.y = acc[i][1] + bv[1];
            v0.z = acc[i][2] + bv[2]; v0.w = acc[i][3] + bv[3];
            v1.x = acc[i][4] + bv[4]; v1.y = acc[i][5] + bv[5];
            v1.z = acc[i][6] + bv[6]; v1.w = acc[i][7] + bv[7];
            *(float4*)(C + base)     = v0;
            *(float4*)(C + base + 4) = v1;
        }
    }
}

// ---------------------------------------------------------------------------
// Copy cache K/V (t < 1024) into d_out's new_k/new_v head-major layout.
// ---------------------------------------------------------------------------
__global__ __launch_bounds__(256) void kvcache_copy(
    const float* __restrict__ ck, const float* __restrict__ cv,
    float* __restrict__ out)
{
    const int half = BATCH * NH * CL * 32;  // float4 count per tensor
    int idx = blockIdx.x * blockDim.x + threadIdx.x;
    const float* src;
    float* dst;
    int i;
    if (idx < half) { src = ck; dst = out + OFF_K; i = idx; }
    else            { src = cv; dst = out + OFF_V; i = idx - half; }
    int d4 = i & 31;
    int t  = (i >> 5) & 1023;
    int h  = (i >> 15) & 15;
    int b  = i >> 19;
    float4 v = *(const float4*)(src + ((size_t)(b * CL + t) * DM) + h * HD + d4 * 4);
    *(float4*)(dst + (((size_t)(b * NH + h) * 2048) + t) * HD + d4 * 4) = v;
}

// ---------------------------------------------------------------------------
// Flash attention: Q[b,h, 1024,128] vs cache K/V only, causal.
// BQ = BK = 64, 256 threads, fp32, XOR-swizzled smem (float4 granularity).
// ---------------------------------------------------------------------------
__device__ __forceinline__ int swz(int row, int d4) {
    return row * 32 + (d4 ^ (((row >> 2) & 7) << 2));
}

__global__ __launch_bounds__(256) void attn_kernel(
    const float* __restrict__ Q, const float* __restrict__ Kc,
    const float* __restrict__ Vc, float* __restrict__ O)
{
    extern __shared__ float sm[];
    float4* Qs = (float4*)sm;            // 64*32 float4
    float4* Ks = Qs + 64 * 32;
    float4* Vs = Ks + 64 * 32;
    float* Ps   = (float*)(Vs + 64 * 32);   // 64 x 65
    float* mrow = Ps + 64 * 65;
    float* lrow = mrow + 64;
    float* crow = lrow + 64;
    float* pmax = crow + 64;             // 64*4
    float* psum = pmax + 256;            // 64*4

    const int tid = threadIdx.x;
    const int qt = blockIdx.x, h = blockIdx.y, b = blockIdx.z;
    const int tr = tid >> 4, tc = tid & 15;
    const int rS = tid >> 2, q4 = tid & 3;
    const float inv_scale = 0.088388347648318447f;  // 1/sqrt(128)

    const float* Qbase = Q + ((size_t)b * TQL + qt * 64) * DM + h * HD;
    const float* Kbase = Kc + (size_t)b * CL * DM + h * HD;
    const float* Vbase = Vc + (size_t)b * CL * DM + h * HD;

#pragma unroll
    for (int i = 0; i < 8; i++) {
        int l = tid + 256 * i;
        int r = l >> 5, d4 = l & 31;
        float4 q = *(const float4*)(Qbase + (size_t)r * DM + d4 * 4);
        q.x *= inv_scale; q.y *= inv_scale; q.z *= inv_scale; q.w *= inv_scale;
        Qs[swz(r, d4)] = q;
    }
    if (tid < 64) { mrow[tid] = -1e30f; lrow[tid] = 0.f; }

    float acc[4][8];
#pragma unroll
    for (int i = 0; i < 4; i++)
#pragma unroll
        for (int j = 0; j < 8; j++) acc[i][j] = 0.f;

    for (int kt = 0; kt <= qt; kt++) {
        __syncthreads();
#pragma unroll
        for (int i = 0; i < 8; i++) {
            int l = tid + 256 * i;
            int r = l >> 5, d4 = l & 31;
            Ks[swz(r, d4)] = *(const float4*)(Kbase + (size_t)(kt * 64 + r) * DM + d4 * 4);
            Vs[swz(r, d4)] = *(const float4*)(Vbase + (size_t)(kt * 64 + r) * DM + d4 * 4);
        }
        __syncthreads();

        float s[4][4];
#pragma unroll
        for (int i = 0; i < 4; i++)
#pragma unroll
            for (int j = 0; j < 4; j++) s[i][j] = 0.f;

#pragma unroll 4
        for (int d4 = 0; d4 < 32; d4++) {
            float4 qv[4], kv[4];
#pragma unroll
            for (int i = 0; i < 4; i++) qv[i] = Qs[swz(tr * 4 + i, d4)];
#pragma unroll
            for (int j = 0; j < 4; j++) kv[j] = Ks[swz(tc * 4 + j, d4)];
#pragma unroll
            for (int i = 0; i < 4; i++)
#pragma unroll
                for (int j = 0; j < 4; j++)
                    s[i][j] += qv[i].x * kv[j].x + qv[i].y * kv[j].y
                             + qv[i].z * kv[j].z + qv[i].w * kv[j].w;
        }
        if (kt == qt) {
#pragma unroll
            for (int i = 0; i < 4; i++)
#pragma unroll
                for (int j = 0; j < 4; j++)
                    if (tc * 4 + j > tr * 4 + i) s[i][j] = -1e30f;
        }
#pragma unroll
        for (int i = 0; i < 4; i++)
#pragma unroll
            for (int j = 0; j < 4; j++)
                Ps[(tr * 4 + i) * 65 + tc * 4 + j] = s[i][j];
        __syncthreads();

        // per-row partial max over 16 cols
        float tm = -1e30f;
#pragma unroll
        for (int c = 0; c < 16; c++) tm = fmaxf(tm, Ps[rS * 65 + q4 * 16 + c]);
        pmax[rS * 4 + q4] = tm;
        __syncthreads();
        if (q4 == 0) {
            float mn = fmaxf(fmaxf(pmax[rS * 4], pmax[rS * 4 + 1]),
                             fmaxf(pmax[rS * 4 + 2], pmax[rS * 4 + 3]));
            mn = fmaxf(mn, mrow[rS]);
            crow[rS] = __expf(mrow[rS] - mn);
            mrow[rS] = mn;
        }
        __syncthreads();
        float mn = mrow[rS];
        float sum = 0.f;
#pragma unroll
        for (int c = 0; c < 16; c++) {
            float p = __expf(Ps[rS * 65 + q4 * 16 + c] - mn);
            Ps[rS * 65 + q4 * 16 + c] = p;
            sum += p;
        }
        psum[rS * 4 + q4] = sum;
        __syncthreads();
        if (q4 == 0)
            lrow[rS] = lrow[rS] * crow[rS]
                     + psum[rS * 4] + psum[rS * 4 + 1]
                     + psum[rS * 4 + 2] + psum[rS * 4 + 3];

        float cf[4];
#pragma unroll
        for (int i = 0; i < 4; i++) cf[i] = crow[tr * 4 + i];
#pragma unroll
        for (int i = 0; i < 4; i++)
#pragma unroll
            for (int j = 0; j < 8; j++) acc[i][j] *= cf[i];

#pragma unroll 8
        for (int c = 0; c < 64; c++) {
            float pv[4];
#pragma unroll
            for (int i = 0; i < 4; i++) pv[i] = Ps[(tr * 4 + i) * 65 + c];
            float4 v0 = Vs[swz(c, tc * 2)];
            float4 v1 = Vs[swz(c, tc * 2 + 1)];
#pragma unroll
            for (int i = 0; i < 4; i++) {
                acc[i][0] += pv[i] * v0.x; acc[i][1] += pv[i] * v0.y;
                acc[i][2] += pv[i] * v0.z; acc[i][3] += pv[i] * v0.w;
                acc[i][4] += pv[i] * v1.x; acc[i][5] += pv[i] * v1.y;
                acc[i][6] += pv[i] * v1.z; acc[i][7] += pv[i] * v1.w;
            }
        }
    }
    __syncthreads();

    float linv[4];
#pragma unroll
    for (int i = 0; i < 4; i++) linv[i] = 1.f / lrow[tr * 4 + i];
    float* Ob = O + ((size_t)b * TQL + qt * 64) * DM + h * HD;
#pragma unroll
    for (int i = 0; i < 4; i++) {
        float4 o0, o1;
        o0.x = acc[i][0] * linv[i]; o0.y = acc[i][1] * linv[i];
        o0.z = acc[i][2] * linv[i]; o0.w = acc[i][3] * linv[i];
        o1.x = acc[i][4] * linv[i]; o1.y = acc[i][5] * linv[i];
        o1.z = acc[i][6] * linv[i]; o1.w = acc[i][7] * linv[i];
        *(float4*)(Ob + (size_t)(tr * 4 + i) * DM + tc * 8)     = o0;
        *(float4*)(Ob + (size_t)(tr * 4 + i) * DM + tc * 8 + 4) = o1;
    }
}

// ---------------------------------------------------------------------------
extern "C" void kernel_launch(void* const* d_in, const int* in_sizes, int n_in,
                              void* d_out, int out_size)
{
    (void)in_sizes; (void)n_in; (void)out_size;
    const float* query       = (const float*)d_in[0];
    const float* key         = (const float*)d_in[1];
    const float* value       = (const float*)d_in[2];
    const float* cache_key   = (const float*)d_in[3];
    const float* cache_value = (const float*)d_in[4];
    const float* Wq = (const float*)d_in[5];
    const float* bq = (const float*)d_in[6];
    const float* Wk = (const float*)d_in[7];
    const float* bk = (const float*)d_in[8];
    const float* Wv = (const float*)d_in[9];
    const float* bv = (const float*)d_in[10];
    const float* Wo = (const float*)d_in[11];
    const float* bo = (const float*)d_in[12];
    float* out = (float*)d_out;

    float *gQ = nullptr, *gctx = nullptr;
    cudaGetSymbolAddress((void**)&gQ, g_Q);
    cudaGetSymbolAddress((void**)&gctx, g_ctx);

    const int ATTN_SMEM = (64*32*4*3) * 4 + (64*65 + 64*3 + 512) * 4;  // 117760
    cudaFuncSetAttribute(attn_kernel, cudaFuncAttributeMaxDynamicSharedMemorySize,
                         ATTN_SMEM);

    dim3 gg(16, 32);
    // Q projection -> scratch
    sgemm_bias<<<gg, 256>>>(query, Wq, bq, gQ, 0);
    // K/V projections -> directly into new_k/new_v (t >= 1024 half)
    sgemm_bias<<<gg, 256>>>(key, Wk, bk, out + OFF_K, 1);
    sgemm_bias<<<gg, 256>>>(value, Wv, bv, out + OFF_V, 1);
    // cache halves of new_k/new_v
    kvcache_copy<<<16384, 256>>>(cache_key, cache_value, out);
    // attention (cache only — the tril(1024,2048) mask never reaches new K/V)
    dim3 ga(16, 16, 4);
    attn_kernel<<<ga, 256, ATTN_SMEM>>>(gQ, cache_key, cache_value, gctx);
    // output projection
    sgemm_bias<<<gg, 256>>>(gctx, Wo, bo, out, 0);
}

// round 8
// speedup vs baseline: 1.6157x; 1.6157x over previous
#include <cuda_runtime.h>
#include <cuda_bf16.h>
#include <cstdint>

#define DM     2048
#define NH     16
#define HD     128
#define BATCH  4
#define TQL    1024
#define CL     1024
#define OFF_K  ((size_t)BATCH*TQL*DM)
#define OFF_V  (OFF_K + (size_t)BATCH*NH*2048*HD)

__device__ float g_Q[BATCH*TQL*DM];
__device__ float g_ctx[BATCH*TQL*DM];
__device__ __nv_bfloat16 g_Ah[(size_t)4096*2048];
__device__ __nv_bfloat16 g_Al[(size_t)4096*2048];
__device__ __nv_bfloat16 g_Wh[(size_t)2048*2048];
__device__ __nv_bfloat16 g_Wl[(size_t)2048*2048];

// ============================================================================
// helpers (family-safe PTX only: cp.async, ldmatrix, mma.sync — no tcgen05)
// ============================================================================
__device__ __forceinline__ uint32_t smem_u32(const void* p) {
    uint32_t a;
    asm("{ .reg .u64 t; cvta.to.shared.u64 t, %1; cvt.u32.u64 %0, t; }"
        : "=r"(a) : "l"(p));
    return a;
}
__device__ __forceinline__ uint32_t sw128o(uint32_t o) {
    return o ^ ((o >> 3) & 0x70);
}
__device__ __forceinline__ void cp16(uint32_t saddr, const void* g) {
    asm volatile("cp.async.cg.shared.global [%0], [%1], 16;"
                 :: "r"(saddr), "l"(g) : "memory");
}
__device__ __forceinline__ void cp_commit() {
    asm volatile("cp.async.commit_group;" ::: "memory");
}
template<int N> __device__ __forceinline__ void cp_wait() {
    asm volatile("cp.async.wait_group %0;" :: "n"(N) : "memory");
}
#define LDMX4(r, addr) \
    asm volatile("ldmatrix.sync.aligned.m8n8.x4.shared.b16 {%0,%1,%2,%3}, [%4];" \
        : "=r"((r)[0]), "=r"((r)[1]), "=r"((r)[2]), "=r"((r)[3]) : "r"(addr))
#define MMA16816(c, a, b0, b1) \
    asm volatile("mma.sync.aligned.m16n8k16.row.col.f32.bf16.bf16.f32 " \
        "{%0,%1,%2,%3}, {%4,%5,%6,%7}, {%8,%9}, {%0,%1,%2,%3};" \
        : "+f"((c)[0]), "+f"((c)[1]), "+f"((c)[2]), "+f"((c)[3]) \
        : "r"((a)[0]), "r"((a)[1]), "r"((a)[2]), "r"((a)[3]), "r"(b0), "r"(b1))

// ============================================================================
// fp32 -> (bf16 hi, bf16 lo) split pre-pass. 8 floats per thread.
// ============================================================================
__global__ __launch_bounds__(256) void conv_split(
    const float* __restrict__ src, __nv_bfloat16* __restrict__ hi,
    __nv_bfloat16* __restrict__ lo)
{
    size_t i = ((size_t)blockIdx.x * 256 + threadIdx.x) * 8;
    float4 a = *(const float4*)(src + i);
    float4 b = *(const float4*)(src + i + 4);
    float v[8] = {a.x, a.y, a.z, a.w, b.x, b.y, b.z, b.w};
    uint32_t h[4], l[4];
#pragma unroll
    for (int j = 0; j < 4; j++) {
        __nv_bfloat162 h2 = __floats2bfloat162_rn(v[2*j], v[2*j+1]);
        float r0 = v[2*j]   - __bfloat162float(__low2bfloat16(h2));
        float r1 = v[2*j+1] - __bfloat162float(__high2bfloat16(h2));
        __nv_bfloat162 l2 = __floats2bfloat162_rn(r0, r1);
        h[j] = *reinterpret_cast<uint32_t*>(&h2);
        l[j] = *reinterpret_cast<uint32_t*>(&l2);
    }
    *(uint4*)(hi + i) = make_uint4(h[0], h[1], h[2], h[3]);
    *(uint4*)(lo + i) = make_uint4(l[0], l[1], l[2], l[3]);
}

// ============================================================================
// Split-bf16 GEMM via mma.sync: C[4096,2048] = A @ W^T + bias (fp32 out).
// CTA 128x128, K-stage 64, 8 warps (2x4, warp tile 64x32), cp.async double buf.
// mode 0: row-major C; mode 1: kv-cache layout (t >= 1024 half).
// ============================================================================
#define KT 64
#define TILE_B 16384                 // 128 rows x 128B (bf16 64 cols)
#define STAGE_B (4*TILE_B)           // Ah, Al, Wh, Wl

__global__ __launch_bounds__(256) void gemm_mma(
    const __nv_bfloat16* __restrict__ Ah, const __nv_bfloat16* __restrict__ Al,
    const __nv_bfloat16* __restrict__ Wh, const __nv_bfloat16* __restrict__ Wl,
    const float* __restrict__ bias, float* __restrict__ C, int mode)
{
    extern __shared__ __align__(1024) char smem[];
    const uint32_t sb = smem_u32(smem);
    const int tid  = threadIdx.x;
    const int lane = tid & 31, wid = tid >> 5;
    const int wm = wid >> 2, wn = wid & 3;
    const int bn = blockIdx.x, bm = blockIdx.y;
    const int rowA0 = bm * 128, rowW0 = bn * 128;

    // cp.async mapping: per tile, thread loads 4x16B: row = tid>>1, chunk (tid&1)*4+i
    const int crow = tid >> 1;
    const int cc   = (tid & 1) * 4;
    const char* pAh = (const char*)(Ah + (size_t)(rowA0 + crow) * DM) + cc * 16;
    const char* pAl = (const char*)(Al + (size_t)(rowA0 + crow) * DM) + cc * 16;
    const char* pWh = (const char*)(Wh + (size_t)(rowW0 + crow) * DM) + cc * 16;
    const char* pWl = (const char*)(Wl + (size_t)(rowW0 + crow) * DM) + cc * 16;

    float c[4][4][4];
#pragma unroll
    for (int mi = 0; mi < 4; mi++)
#pragma unroll
        for (int ni = 0; ni < 4; ni++)
#pragma unroll
            for (int k = 0; k < 4; k++) c[mi][ni][k] = 0.f;

    auto issue = [&](int s) {
        uint32_t sbuf = sb + (s & 1) * STAGE_B;
        size_t gk = (size_t)s * KT * 2;   // byte offset along K
#pragma unroll
        for (int i = 0; i < 4; i++) {
            uint32_t so = sw128o((uint32_t)(crow * 128 + (cc + i) * 16));
            cp16(sbuf + so,              pAh + gk + i * 16);
            cp16(sbuf + TILE_B + so,     pAl + gk + i * 16);
            cp16(sbuf + 2 * TILE_B + so, pWh + gk + i * 16);
            cp16(sbuf + 3 * TILE_B + so, pWl + gk + i * 16);
        }
    };

    const int lrow = lane & 15;
    const int lc16 = (lane >> 4) * 16;

    issue(0); cp_commit();
    for (int s = 0; s < 32; s++) {
        if (s + 1 < 32) { issue(s + 1); cp_commit(); cp_wait<1>(); }
        else            { cp_wait<0>(); }
        __syncthreads();

        const uint32_t base = sb + (s & 1) * STAGE_B;
#pragma unroll
        for (int ks = 0; ks < 4; ks++) {
            const uint32_t bo = ks * 32 + lc16;
            uint32_t ah[4][4], al[4][4], wh[2][4], wl[2][4];
#pragma unroll
            for (int mi = 0; mi < 4; mi++) {
                uint32_t ro = (uint32_t)((wm * 64 + mi * 16 + lrow) * 128 + bo);
                LDMX4(ah[mi], base + sw128o(ro));
                LDMX4(al[mi], base + TILE_B + sw128o(ro));
            }
#pragma unroll
            for (int nj = 0; nj < 2; nj++) {
                uint32_t ro = (uint32_t)((wn * 32 + nj * 16 + lrow) * 128 + bo);
                LDMX4(wh[nj], base + 2 * TILE_B + sw128o(ro));
                LDMX4(wl[nj], base + 3 * TILE_B + sw128o(ro));
            }
#pragma unroll
            for (int mi = 0; mi < 4; mi++)
#pragma unroll
                for (int ni = 0; ni < 4; ni++) {
                    const int nj = ni >> 1, sel = ni & 1;
                    MMA16816(c[mi][ni], ah[mi], wh[nj][sel], wh[nj][sel + 2]);
                    MMA16816(c[mi][ni], ah[mi], wl[nj][sel], wl[nj][sel + 2]);
                    MMA16816(c[mi][ni], al[mi], wh[nj][sel], wh[nj][sel + 2]);
                }
        }
        if (s + 1 < 32) __syncthreads();
    }

    // epilogue
    const int r0 = rowA0 + wm * 64 + (lane >> 2);
#pragma unroll
    for (int mi = 0; mi < 4; mi++) {
#pragma unroll
        for (int ni = 0; ni < 4; ni++) {
            int row = r0 + mi * 16;
            int ncol = bn * 128 + wn * 32 + ni * 8 + (lane & 3) * 2;
            float b0 = bias[ncol], b1 = bias[ncol + 1];
            float2 v0 = make_float2(c[mi][ni][0] + b0, c[mi][ni][1] + b1);
            float2 v1 = make_float2(c[mi][ni][2] + b0, c[mi][ni][3] + b1);
            if (mode == 0) {
                *(float2*)(C + (size_t)row * DM + ncol)       = v0;
                *(float2*)(C + (size_t)(row + 8) * DM + ncol) = v1;
            } else {
                int bi = row >> 10, t = row & 1023;
                int dh = wn * 32 + ni * 8 + (lane & 3) * 2;
                size_t d0 = (((size_t)(bi * NH + bn) * 2048) + CL + t) * HD + dh;
                *(float2*)(C + d0)            = v0;
                *(float2*)(C + d0 + 8 * HD)   = v1;
            }
        }
    }
}

// ============================================================================
// Copy cache K/V (t < 1024) into d_out's new_k/new_v head-major layout.
// ============================================================================
__global__ __launch_bounds__(256) void kvcache_copy(
    const float* __restrict__ ck, const float* __restrict__ cv,
    float* __restrict__ out)
{
    const int half = BATCH * NH * CL * 32;
    int idx = blockIdx.x * blockDim.x + threadIdx.x;
    const float* src;
    float* dst;
    int i;
    if (idx < half) { src = ck; dst = out + OFF_K; i = idx; }
    else            { src = cv; dst = out + OFF_V; i = idx - half; }
    int d4 = i & 31;
    int t  = (i >> 5) & 1023;
    int h  = (i >> 15) & 15;
    int b  = i >> 19;
    float4 v = *(const float4*)(src + ((size_t)(b * CL + t) * DM) + h * HD + d4 * 4);
    *(float4*)(dst + (((size_t)(b * NH + h) * 2048) + t) * HD + d4 * 4) = v;
}

// ============================================================================
// Flash attention (fp32): Q vs cache K/V only, causal. BQ=BK=64, 256 thr.
// ============================================================================
__device__ __forceinline__ int swz(int row, int d4) {
    return row * 32 + (d4 ^ (((row >> 2) & 7) << 2));
}

__global__ __launch_bounds__(256) void attn_kernel(
    const float* __restrict__ Q, const float* __restrict__ Kc,
    const float* __restrict__ Vc, float* __restrict__ O)
{
    extern __shared__ float sm[];
    float4* Qs = (float4*)sm;
    float4* Ks = Qs + 64 * 32;
    float4* Vs = Ks + 64 * 32;
    float* Ps   = (float*)(Vs + 64 * 32);
    float* mrow = Ps + 64 * 65;
    float* lrow = mrow + 64;
    float* crow = lrow + 64;
    float* pmax = crow + 64;
    float* psum = pmax + 256;

    const int tid = threadIdx.x;
    const int qt = blockIdx.x, h = blockIdx.y, b = blockIdx.z;
    const int tr = tid >> 4, tc = tid & 15;
    const int rS = tid >> 2, q4 = tid & 3;
    const float inv_scale = 0.088388347648318447f;

    const float* Qbase = Q + ((size_t)b * TQL + qt * 64) * DM + h * HD;
    const float* Kbase = Kc + (size_t)b * CL * DM + h * HD;
    const float* Vbase = Vc + (size_t)b * CL * DM + h * HD;

#pragma unroll
    for (int i = 0; i < 8; i++) {
        int l = tid + 256 * i;
        int r = l >> 5, d4 = l & 31;
        float4 q = *(const float4*)(Qbase + (size_t)r * DM + d4 * 4);
        q.x *= inv_scale; q.y *= inv_scale; q.z *= inv_scale; q.w *= inv_scale;
        Qs[swz(r, d4)] = q;
    }
    if (tid < 64) { mrow[tid] = -1e30f; lrow[tid] = 0.f; }

    float acc[4][8];
#pragma unroll
    for (int i = 0; i < 4; i++)
#pragma unroll
        for (int j = 0; j < 8; j++) acc[i][j] = 0.f;

    for (int kt = 0; kt <= qt; kt++) {
        __syncthreads();
#pragma unroll
        for (int i = 0; i < 8; i++) {
            int l = tid + 256 * i;
            int r = l >> 5, d4 = l & 31;
            Ks[swz(r, d4)] = *(const float4*)(Kbase + (size_t)(kt * 64 + r) * DM + d4 * 4);
            Vs[swz(r, d4)] = *(const float4*)(Vbase + (size_t)(kt * 64 + r) * DM + d4 * 4);
        }
        __syncthreads();

        float s[4][4];
#pragma unroll
        for (int i = 0; i < 4; i++)
#pragma unroll
            for (int j = 0; j < 4; j++) s[i][j] = 0.f;

#pragma unroll 4
        for (int d4 = 0; d4 < 32; d4++) {
            float4 qv[4], kv[4];
#pragma unroll
            for (int i = 0; i < 4; i++) qv[i] = Qs[swz(tr * 4 + i, d4)];
#pragma unroll
            for (int j = 0; j < 4; j++) kv[j] = Ks[swz(tc * 4 + j, d4)];
#pragma unroll
            for (int i = 0; i < 4; i++)
#pragma unroll
                for (int j = 0; j < 4; j++)
                    s[i][j] += qv[i].x * kv[j].x + qv[i].y * kv[j].y
                             + qv[i].z * kv[j].z + qv[i].w * kv[j].w;
        }
        if (kt == qt) {
#pragma unroll
            for (int i = 0; i < 4; i++)
#pragma unroll
                for (int j = 0; j < 4; j++)
                    if (tc * 4 + j > tr * 4 + i) s[i][j] = -1e30f;
        }
#pragma unroll
        for (int i = 0; i < 4; i++)
#pragma unroll
            for (int j = 0; j < 4; j++)
                Ps[(tr * 4 + i) * 65 + tc * 4 + j] = s[i][j];
        __syncthreads();

        float tm = -1e30f;
#pragma unroll
        for (int cI = 0; cI < 16; cI++) tm = fmaxf(tm, Ps[rS * 65 + q4 * 16 + cI]);
        pmax[rS * 4 + q4] = tm;
        __syncthreads();
        if (q4 == 0) {
            float mn = fmaxf(fmaxf(pmax[rS * 4], pmax[rS * 4 + 1]),
                             fmaxf(pmax[rS * 4 + 2], pmax[rS * 4 + 3]));
            mn = fmaxf(mn, mrow[rS]);
            crow[rS] = __expf(mrow[rS] - mn);
            mrow[rS] = mn;
        }
        __syncthreads();
        float mn = mrow[rS];
        float sum = 0.f;
#pragma unroll
        for (int cI = 0; cI < 16; cI++) {
            float p = __expf(Ps[rS * 65 + q4 * 16 + cI] - mn);
            Ps[rS * 65 + q4 * 16 + cI] = p;
            sum += p;
        }
        psum[rS * 4 + q4] = sum;
        __syncthreads();
        if (q4 == 0)
            lrow[rS] = lrow[rS] * crow[rS]
                     + psum[rS * 4] + psum[rS * 4 + 1]
                     + psum[rS * 4 + 2] + psum[rS * 4 + 3];

        float cf[4];
#pragma unroll
        for (int i = 0; i < 4; i++) cf[i] = crow[tr * 4 + i];
#pragma unroll
        for (int i = 0; i < 4; i++)
#pragma unroll
            for (int j = 0; j < 8; j++) acc[i][j] *= cf[i];

#pragma unroll 8
        for (int cI = 0; cI < 64; cI++) {
            float pv[4];
#pragma unroll
            for (int i = 0; i < 4; i++) pv[i] = Ps[(tr * 4 + i) * 65 + cI];
            float4 v0 = Vs[swz(cI, tc * 2)];
            float4 v1 = Vs[swz(cI, tc * 2 + 1)];
#pragma unroll
            for (int i = 0; i < 4; i++) {
                acc[i][0] += pv[i] * v0.x; acc[i][1] += pv[i] * v0.y;
                acc[i][2] += pv[i] * v0.z; acc[i][3] += pv[i] * v0.w;
                acc[i][4] += pv[i] * v1.x; acc[i][5] += pv[i] * v1.y;
                acc[i][6] += pv[i] * v1.z; acc[i][7] += pv[i] * v1.w;
            }
        }
    }
    __syncthreads();

    float linv[4];
#pragma unroll
    for (int i = 0; i < 4; i++) linv[i] = 1.f / lrow[tr * 4 + i];
    float* Ob = O + ((size_t)b * TQL + qt * 64) * DM + h * HD;
#pragma unroll
    for (int i = 0; i < 4; i++) {
        float4 o0, o1;
        o0.x = acc[i][0] * linv[i]; o0.y = acc[i][1] * linv[i];
        o0.z = acc[i][2] * linv[i]; o0.w = acc[i][3] * linv[i];
        o1.x = acc[i][4] * linv[i]; o1.y = acc[i][5] * linv[i];
        o1.z = acc[i][6] * linv[i]; o1.w = acc[i][7] * linv[i];
        *(float4*)(Ob + (size_t)(tr * 4 + i) * DM + tc * 8)     = o0;
        *(float4*)(Ob + (size_t)(tr * 4 + i) * DM + tc * 8 + 4) = o1;
    }
}

// ============================================================================
extern "C" void kernel_launch(void* const* d_in, const int* in_sizes, int n_in,
                              void* d_out, int out_size)
{
    (void)in_sizes; (void)n_in; (void)out_size;
    const float* query       = (const float*)d_in[0];
    const float* key         = (const float*)d_in[1];
    const float* value       = (const float*)d_in[2];
    const float* cache_key   = (const float*)d_in[3];
    const float* cache_value = (const float*)d_in[4];
    const float* Wq = (const float*)d_in[5];
    const float* bq = (const float*)d_in[6];
    const float* Wk = (const float*)d_in[7];
    const float* bk = (const float*)d_in[8];
    const float* Wv = (const float*)d_in[9];
    const float* bv = (const float*)d_in[10];
    const float* Wo = (const float*)d_in[11];
    const float* bo = (const float*)d_in[12];
    float* out = (float*)d_out;

    float *gQ = nullptr, *gctx = nullptr;
    __nv_bfloat16 *ah, *al, *wh, *wl;
    cudaGetSymbolAddress((void**)&gQ, g_Q);
    cudaGetSymbolAddress((void**)&gctx, g_ctx);
    cudaGetSymbolAddress((void**)&ah, g_Ah);
    cudaGetSymbolAddress((void**)&al, g_Al);
    cudaGetSymbolAddress((void**)&wh, g_Wh);
    cudaGetSymbolAddress((void**)&wl, g_Wl);

    const int GEMM_SMEM = 2 * STAGE_B;  // 131072
    cudaFuncSetAttribute(gemm_mma, cudaFuncAttributeMaxDynamicSharedMemorySize,
                         GEMM_SMEM);
    const int ATTN_SMEM = (64*32*4*3) * 4 + (64*65 + 64*3 + 512) * 4;
    cudaFuncSetAttribute(attn_kernel, cudaFuncAttributeMaxDynamicSharedMemorySize,
                         ATTN_SMEM);

    dim3 gg(16, 32);
    // Q projection
    conv_split<<<4096, 256>>>(query, ah, al);
    conv_split<<<2048, 256>>>(Wq, wh, wl);
    gemm_mma<<<gg, 256, GEMM_SMEM>>>(ah, al, wh, wl, bq, gQ, 0);
    // K projection -> new_k (t >= 1024)
    conv_split<<<4096, 256>>>(key, ah, al);
    conv_split<<<2048, 256>>>(Wk, wh, wl);
    gemm_mma<<<gg, 256, GEMM_SMEM>>>(ah, al, wh, wl, bk, out + OFF_K, 1);
    // V projection -> new_v (t >= 1024)
    conv_split<<<4096, 256>>>(value, ah, al);
    conv_split<<<2048, 256>>>(Wv, wh, wl);
    gemm_mma<<<gg, 256, GEMM_SMEM>>>(ah, al, wh, wl, bv, out + OFF_V, 1);
    // cache halves of new_k/new_v
    kvcache_copy<<<16384, 256>>>(cache_key, cache_value, out);
    // attention (cache only — the tril(1024,2048) mask never reaches new K/V)
    dim3 ga(16, 16, 4);
    attn_kernel<<<ga, 256, ATTN_SMEM>>>(gQ, cache_key, cache_value, gctx);
    // output projection
    conv_split<<<4096, 256>>>(gctx, ah, al);
    conv_split<<<2048, 256>>>(Wo, wh, wl);
    gemm_mma<<<gg, 256, GEMM_SMEM>>>(ah, al, wh, wl, bo, out, 0);
}

// round 9
// speedup vs baseline: 2.2800x; 1.4111x over previous
#include <cuda_runtime.h>
#include <cuda_bf16.h>
#include <cstdint>

#define DM     2048
#define NH     16
#define HD     128
#define BATCH  4
#define TQL    1024
#define CL     1024
#define OFF_K  ((size_t)BATCH*TQL*DM)
#define OFF_V  (OFF_K + (size_t)BATCH*NH*2048*HD)

__device__ __nv_bfloat16 g_Ah[(size_t)4096*2048];
__device__ __nv_bfloat16 g_Al[(size_t)4096*2048];
__device__ __nv_bfloat16 g_Wh[(size_t)2048*2048];
__device__ __nv_bfloat16 g_Wl[(size_t)2048*2048];
__device__ __nv_bfloat16 g_Qh[(size_t)4096*2048];
__device__ __nv_bfloat16 g_Ql[(size_t)4096*2048];
__device__ __nv_bfloat16 g_cKh[(size_t)4096*2048];
__device__ __nv_bfloat16 g_cKl[(size_t)4096*2048];
__device__ __nv_bfloat16 g_cVh[(size_t)4096*2048];
__device__ __nv_bfloat16 g_cVl[(size_t)4096*2048];

// ============================================================================
// helpers (family-safe PTX only)
// ============================================================================
__device__ __forceinline__ uint32_t smem_u32(const void* p) {
    uint32_t a;
    asm("{ .reg .u64 t; cvta.to.shared.u64 t, %1; cvt.u32.u64 %0, t; }"
        : "=r"(a) : "l"(p));
    return a;
}
__device__ __forceinline__ uint32_t sw128o(uint32_t o) {
    return o ^ ((o >> 3) & 0x70);
}
__device__ __forceinline__ void cp16(uint32_t saddr, const void* g) {
    asm volatile("cp.async.cg.shared.global [%0], [%1], 16;"
                 :: "r"(saddr), "l"(g) : "memory");
}
__device__ __forceinline__ void cp_commit() {
    asm volatile("cp.async.commit_group;" ::: "memory");
}
template<int N> __device__ __forceinline__ void cp_wait() {
    asm volatile("cp.async.wait_group %0;" :: "n"(N) : "memory");
}
#define LDMX4(r, addr) \
    asm volatile("ldmatrix.sync.aligned.m8n8.x4.shared.b16 {%0,%1,%2,%3}, [%4];" \
        : "=r"((r)[0]), "=r"((r)[1]), "=r"((r)[2]), "=r"((r)[3]) : "r"(addr))
#define LDMX4T(r, addr) \
    asm volatile("ldmatrix.sync.aligned.m8n8.x4.trans.shared.b16 {%0,%1,%2,%3}, [%4];" \
        : "=r"((r)[0]), "=r"((r)[1]), "=r"((r)[2]), "=r"((r)[3]) : "r"(addr))
#define MMA16816(c, a, b0, b1) \
    asm volatile("mma.sync.aligned.m16n8k16.row.col.f32.bf16.bf16.f32 " \
        "{%0,%1,%2,%3}, {%4,%5,%6,%7}, {%8,%9}, {%0,%1,%2,%3};" \
        : "+f"((c)[0]), "+f"((c)[1]), "+f"((c)[2]), "+f"((c)[3]) \
        : "r"((a)[0]), "r"((a)[1]), "r"((a)[2]), "r"((a)[3]), "r"(b0), "r"(b1))

__device__ __forceinline__ void split2(float v0, float v1,
                                       __nv_bfloat162& h2, __nv_bfloat162& l2) {
    h2 = __floats2bfloat162_rn(v0, v1);
    float r0 = v0 - __bfloat162float(__low2bfloat16(h2));
    float r1 = v1 - __bfloat162float(__high2bfloat16(h2));
    l2 = __floats2bfloat162_rn(r0, r1);
}

// ============================================================================
// fp32 -> (bf16 hi, bf16 lo) split pre-pass. 8 floats per thread.
// ============================================================================
__global__ __launch_bounds__(256) void conv_split(
    const float* __restrict__ src, __nv_bfloat16* __restrict__ hi,
    __nv_bfloat16* __restrict__ lo)
{
    size_t i = ((size_t)blockIdx.x * 256 + threadIdx.x) * 8;
    float4 a = *(const float4*)(src + i);
    float4 b = *(const float4*)(src + i + 4);
    float v[8] = {a.x, a.y, a.z, a.w, b.x, b.y, b.z, b.w};
    uint32_t h[4], l[4];
#pragma unroll
    for (int j = 0; j < 4; j++) {
        __nv_bfloat162 h2, l2;
        split2(v[2*j], v[2*j+1], h2, l2);
        h[j] = *reinterpret_cast<uint32_t*>(&h2);
        l[j] = *reinterpret_cast<uint32_t*>(&l2);
    }
    *(uint4*)(hi + i) = make_uint4(h[0], h[1], h[2], h[3]);
    *(uint4*)(lo + i) = make_uint4(l[0], l[1], l[2], l[3]);
}

// ============================================================================
// Split-bf16 GEMM: C[4096,2048] = A @ W^T + bias (fp32 acc).
// CTA 128x128, K-stage 64, 8 warps, cp.async 3-stage pipeline.
// mode 0: fp32 row-major C; mode 1: fp32 kv-cache layout (t>=1024 half);
// mode 2: split bf16 (Ch/Cl), scaled by 1/sqrt(HD)  [Q projection]
// ============================================================================
#define KT 64
#define TILE_B 16384
#define STAGE_B (4*TILE_B)
#define NSTAGE 3

__global__ __launch_bounds__(256) void gemm_mma(
    const __nv_bfloat16* __restrict__ Ah, const __nv_bfloat16* __restrict__ Al,
    const __nv_bfloat16* __restrict__ Wh, const __nv_bfloat16* __restrict__ Wl,
    const float* __restrict__ bias, float* __restrict__ C,
    __nv_bfloat16* __restrict__ Ch, __nv_bfloat16* __restrict__ Cl, int mode)
{
    extern __shared__ __align__(1024) char smem[];
    const uint32_t sb = smem_u32(smem);
    const int tid  = threadIdx.x;
    const int lane = tid & 31, wid = tid >> 5;
    const int wm = wid >> 2, wn = wid & 3;
    const int bn = blockIdx.x, bm = blockIdx.y;
    const int rowA0 = bm * 128, rowW0 = bn * 128;

    const int crow = tid >> 1;
    const int cc   = (tid & 1) * 4;
    const char* pAh = (const char*)(Ah + (size_t)(rowA0 + crow) * DM) + cc * 16;
    const char* pAl = (const char*)(Al + (size_t)(rowA0 + crow) * DM) + cc * 16;
    const char* pWh = (const char*)(Wh + (size_t)(rowW0 + crow) * DM) + cc * 16;
    const char* pWl = (const char*)(Wl + (size_t)(rowW0 + crow) * DM) + cc * 16;

    float c[4][4][4];
#pragma unroll
    for (int mi = 0; mi < 4; mi++)
#pragma unroll
        for (int ni = 0; ni < 4; ni++)
#pragma unroll
            for (int k = 0; k < 4; k++) c[mi][ni][k] = 0.f;

    auto issue = [&](int s) {
        uint32_t sbuf = sb + (s % NSTAGE) * STAGE_B;
        size_t gk = (size_t)s * KT * 2;
#pragma unroll
        for (int i = 0; i < 4; i++) {
            uint32_t so = sw128o((uint32_t)(crow * 128 + (cc + i) * 16));
            cp16(sbuf + so,              pAh + gk + i * 16);
            cp16(sbuf + TILE_B + so,     pAl + gk + i * 16);
            cp16(sbuf + 2 * TILE_B + so, pWh + gk + i * 16);
            cp16(sbuf + 3 * TILE_B + so, pWl + gk + i * 16);
        }
    };

    const int lrow = lane & 15;
    const int lc16 = (lane >> 4) * 16;

    issue(0); cp_commit();
    issue(1); cp_commit();
    for (int s = 0; s < 32; s++) {
        if (s + 2 < 32)      { issue(s + 2); cp_commit(); cp_wait<2>(); }
        else if (s + 1 < 32) { cp_wait<1>(); }
        else                 { cp_wait<0>(); }
        __syncthreads();

        const uint32_t base = sb + (s % NSTAGE) * STAGE_B;
#pragma unroll
        for (int ks = 0; ks < 4; ks++) {
            const uint32_t bo = ks * 32 + lc16;
            uint32_t ah[4][4], al[4][4], wh[2][4], wl[2][4];
#pragma unroll
            for (int mi = 0; mi < 4; mi++) {
                uint32_t ro = (uint32_t)((wm * 64 + mi * 16 + lrow) * 128 + bo);
                LDMX4(ah[mi], base + sw128o(ro));
                LDMX4(al[mi], base + TILE_B + sw128o(ro));
            }
#pragma unroll
            for (int nj = 0; nj < 2; nj++) {
                uint32_t ro = (uint32_t)((wn * 32 + nj * 16 + lrow) * 128 + bo);
                LDMX4(wh[nj], base + 2 * TILE_B + sw128o(ro));
                LDMX4(wl[nj], base + 3 * TILE_B + sw128o(ro));
            }
            // term-major ordering: 16 independent accumulators between reuses
#pragma unroll
            for (int mi = 0; mi < 4; mi++)
#pragma unroll
                for (int ni = 0; ni < 4; ni++) {
                    const int nj = ni >> 1, sel = ni & 1;
                    MMA16816(c[mi][ni], ah[mi], wh[nj][sel], wh[nj][sel + 2]);
                }
#pragma unroll
            for (int mi = 0; mi < 4; mi++)
#pragma unroll
                for (int ni = 0; ni < 4; ni++) {
                    const int nj = ni >> 1, sel = ni & 1;
                    MMA16816(c[mi][ni], ah[mi], wl[nj][sel], wl[nj][sel + 2]);
                }
#pragma unroll
            for (int mi = 0; mi < 4; mi++)
#pragma unroll
                for (int ni = 0; ni < 4; ni++) {
                    const int nj = ni >> 1, sel = ni & 1;
                    MMA16816(c[mi][ni], al[mi], wh[nj][sel], wh[nj][sel + 2]);
                }
        }
        __syncthreads();
    }

    const int r0 = rowA0 + wm * 64 + (lane >> 2);
    const float sc = 0.088388347648318447f;  // 1/sqrt(128)
#pragma unroll
    for (int mi = 0; mi < 4; mi++) {
#pragma unroll
        for (int ni = 0; ni < 4; ni++) {
            int row = r0 + mi * 16;
            int ncol = bn * 128 + wn * 32 + ni * 8 + (lane & 3) * 2;
            float b0 = bias[ncol], b1 = bias[ncol + 1];
            float v0 = c[mi][ni][0] + b0, v1 = c[mi][ni][1] + b1;
            float v2 = c[mi][ni][2] + b0, v3 = c[mi][ni][3] + b1;
            if (mode == 0) {
                *(float2*)(C + (size_t)row * DM + ncol)       = make_float2(v0, v1);
                *(float2*)(C + (size_t)(row + 8) * DM + ncol) = make_float2(v2, v3);
            } else if (mode == 1) {
                int bi = row >> 10, t = row & 1023;
                int dh = wn * 32 + ni * 8 + (lane & 3) * 2;
                size_t d0 = (((size_t)(bi * NH + bn) * 2048) + CL + t) * HD + dh;
                *(float2*)(C + d0)          = make_float2(v0, v1);
                *(float2*)(C + d0 + 8 * HD) = make_float2(v2, v3);
            } else {
                v0 *= sc; v1 *= sc; v2 *= sc; v3 *= sc;
                __nv_bfloat162 h2, l2;
                split2(v0, v1, h2, l2);
                *(__nv_bfloat162*)(Ch + (size_t)row * DM + ncol) = h2;
                *(__nv_bfloat162*)(Cl + (size_t)row * DM + ncol) = l2;
                split2(v2, v3, h2, l2);
                *(__nv_bfloat162*)(Ch + (size_t)(row + 8) * DM + ncol) = h2;
                *(__nv_bfloat162*)(Cl + (size_t)(row + 8) * DM + ncol) = l2;
            }
        }
    }
}

// ============================================================================
// Copy cache K/V (t < 1024) into d_out's new_k/new_v head-major layout.
// ============================================================================
__global__ __launch_bounds__(256) void kvcache_copy(
    const float* __restrict__ ck, const float* __restrict__ cv,
    float* __restrict__ out)
{
    const int half = BATCH * NH * CL * 32;
    int idx = blockIdx.x * blockDim.x + threadIdx.x;
    const float* src;
    float* dst;
    int i;
    if (idx < half) { src = ck; dst = out + OFF_K; i = idx; }
    else            { src = cv; dst = out + OFF_V; i = idx - half; }
    int d4 = i & 31;
    int t  = (i >> 5) & 1023;
    int h  = (i >> 15) & 15;
    int b  = i >> 19;
    float4 v = *(const float4*)(src + ((size_t)(b * CL + t) * DM) + h * HD + d4 * 4);
    *(float4*)(dst + (((size_t)(b * NH + h) * 2048) + t) * HD + d4 * 4) = v;
}

// ============================================================================
// HMMA flash attention: split-bf16 QK and PV, fp32 softmax.
// BQ=BK=64, 256 threads (8 warps). Q pre-scaled & pre-split; cache K/V pre-split.
// Output written as split bf16 into g_Ah/g_Al (ctx layout = out-proj A input).
// ============================================================================
#define ATT_SQ   0
#define ATT_SKV  32768
#define ATT_SPS  163840
#define ATT_SPH  180736
#define ATT_SPL  188928
#define ATT_STAT 197120
#define ATT_SMEMSZ 199936

__global__ __launch_bounds__(256) void attn_mma(
    const __nv_bfloat16* __restrict__ Qh, const __nv_bfloat16* __restrict__ Ql,
    const __nv_bfloat16* __restrict__ Kh, const __nv_bfloat16* __restrict__ Kl,
    const __nv_bfloat16* __restrict__ Vh, const __nv_bfloat16* __restrict__ Vl,
    __nv_bfloat16* __restrict__ Oh, __nv_bfloat16* __restrict__ Ol)
{
    extern __shared__ __align__(1024) char smem[];
    const uint32_t sb = smem_u32(smem);
    const int tid = threadIdx.x, lane = tid & 31, wid = tid >> 5;
    const int wm = wid >> 1, wn = wid & 1;
    const int qt = blockIdx.x, h = blockIdx.y, b = blockIdx.z;

    float* Ps   = (float*)(smem + ATT_SPS);      // 64 x 66
    float* mrow = (float*)(smem + ATT_STAT);
    float* lrow = mrow + 64;
    float* crow = mrow + 128;
    float* pmax = mrow + 192;                    // 64*4
    float* psum = mrow + 448;                    // 64*4

    // ---- issue Q tile loads + KV(0) loads, one commit group ----
    const size_t qbase = ((size_t)(b * TQL + qt * 64)) * DM + h * HD;
#pragma unroll
    for (int i = 0; i < 4; i++) {
        int cid = tid + 256 * i;
        int row = cid >> 4, c16 = cid & 15;
        int hf = c16 >> 3;
        uint32_t so = hf * 8192 + sw128o((uint32_t)(row * 128 + (c16 & 7) * 16));
        size_t ge = qbase + (size_t)row * DM + hf * 64 + (c16 & 7) * 8;
        cp16(sb + ATT_SQ + so,         Qh + ge);
        cp16(sb + ATT_SQ + 16384 + so, Ql + ge);
    }
    auto load_kv = [&](int buf, int kt) {
        uint32_t kb = sb + ATT_SKV + buf * 65536;
        size_t base = ((size_t)(b * CL + kt * 64)) * DM + h * HD;
#pragma unroll
        for (int i = 0; i < 4; i++) {
            int cid = tid + 256 * i;
            int row = cid >> 4, c16 = cid & 15;
            int hf = c16 >> 3;
            uint32_t so = hf * 8192 + sw128o((uint32_t)(row * 128 + (c16 & 7) * 16));
            size_t ge = base + (size_t)row * DM + hf * 64 + (c16 & 7) * 8;
            cp16(kb + so,         Kh + ge);
            cp16(kb + 16384 + so, Kl + ge);
            cp16(kb + 32768 + so, Vh + ge);
            cp16(kb + 49152 + so, Vl + ge);
        }
    };
    load_kv(0, 0);
    cp_commit();

    if (tid < 64) { mrow[tid] = -1e30f; lrow[tid] = 0.f; }

    float o[8][4];
#pragma unroll
    for (int ni = 0; ni < 8; ni++)
#pragma unroll
        for (int k = 0; k < 4; k++) o[ni][k] = 0.f;

    const int rS = tid >> 2, q4 = tid & 3;
    const int lr16 = lane & 15, lc16 = (lane >> 4) * 16;
    const int rown = lane >> 2, coln = (lane & 3) * 2;

    for (int kt = 0; kt <= qt; kt++) {
        if (kt < qt) { load_kv((kt + 1) & 1, kt + 1); cp_commit(); cp_wait<1>(); }
        else         { cp_wait<0>(); }
        __syncthreads();

        const uint32_t kb = sb + ATT_SKV + (kt & 1) * 65536;

        // ---- S = Q K^T (3 split products), warp tile 16x32 ----
        float s[4][4];
#pragma unroll
        for (int ni = 0; ni < 4; ni++)
#pragma unroll
            for (int k = 0; k < 4; k++) s[ni][k] = 0.f;

#pragma unroll
        for (int ks = 0; ks < 8; ks++) {
            const int hf = ks >> 2;
            const uint32_t bo = (ks & 3) * 32 + lc16;
            uint32_t a_h[4], a_l[4], bh[2][4], bl[2][4];
            uint32_t qro = sw128o((uint32_t)((wm * 16 + lr16) * 128 + bo));
            LDMX4(a_h, sb + ATT_SQ + hf * 8192 + qro);
            LDMX4(a_l, sb + ATT_SQ + 16384 + hf * 8192 + qro);
#pragma unroll
            for (int nj = 0; nj < 2; nj++) {
                uint32_t kro = sw128o((uint32_t)((wn * 32 + nj * 16 + lr16) * 128 + bo));
                LDMX4(bh[nj], kb + hf * 8192 + kro);
                LDMX4(bl[nj], kb + 16384 + hf * 8192 + kro);
            }
#pragma unroll
            for (int ni = 0; ni < 4; ni++) {
                const int nj = ni >> 1, sel = ni & 1;
                MMA16816(s[ni], a_h, bh[nj][sel], bh[nj][sel + 2]);
            }
#pragma unroll
            for (int ni = 0; ni < 4; ni++) {
                const int nj = ni >> 1, sel = ni & 1;
                MMA16816(s[ni], a_h, bl[nj][sel], bl[nj][sel + 2]);
            }
#pragma unroll
            for (int ni = 0; ni < 4; ni++) {
                const int nj = ni >> 1, sel = ni & 1;
                MMA16816(s[ni], a_l, bh[nj][sel], bh[nj][sel + 2]);
            }
        }
        // store S to smem
        {
            int r1 = wm * 16 + rown;
#pragma unroll
            for (int ni = 0; ni < 4; ni++) {
                int col = wn * 32 + ni * 8 + coln;
                *(float2*)&Ps[r1 * 66 + col]       = make_float2(s[ni][0], s[ni][1]);
                *(float2*)&Ps[(r1 + 8) * 66 + col] = make_float2(s[ni][2], s[ni][3]);
            }
        }
        __syncthreads();

        // ---- scalar softmax: row rS, cols q4*16..+16 ----
        const bool diag = (kt == qt);
        float sl[16];
        float tm = -1e30f;
#pragma unroll
        for (int ci = 0; ci < 16; ci++) {
            int cc = q4 * 16 + ci;
            float v = Ps[rS * 66 + cc];
            if (diag && cc > rS) v = -1e30f;
            sl[ci] = v;
            tm = fmaxf(tm, v);
        }
        pmax[rS * 4 + q4] = tm;
        __syncthreads();
        if (q4 == 0) {
            float mn = fmaxf(fmaxf(pmax[rS * 4], pmax[rS * 4 + 1]),
                             fmaxf(pmax[rS * 4 + 2], pmax[rS * 4 + 3]));
            mn = fmaxf(mn, mrow[rS]);
            crow[rS] = __expf(mrow[rS] - mn);
            mrow[rS] = mn;
        }
        __syncthreads();
        float mn = mrow[rS];
        float sum = 0.f;
#pragma unroll
        for (int ci = 0; ci < 16; ci += 2) {
            int cc = q4 * 16 + ci;
            float p0 = __expf(sl[ci] - mn);
            float p1 = __expf(sl[ci + 1] - mn);
            sum += p0 + p1;
            __nv_bfloat162 h2, l2;
            split2(p0, p1, h2, l2);
            uint32_t off = sw128o((uint32_t)(rS * 128 + cc * 2));
            *(__nv_bfloat162*)(smem + ATT_SPH + off) = h2;
            *(__nv_bfloat162*)(smem + ATT_SPL + off) = l2;
        }
        psum[rS * 4 + q4] = sum;
        __syncthreads();
        if (q4 == 0)
            lrow[rS] = lrow[rS] * crow[rS]
                     + psum[rS * 4] + psum[rS * 4 + 1]
                     + psum[rS * 4 + 2] + psum[rS * 4 + 3];

        // ---- rescale O, then O += P V (3 split products), warp tile 16x64 ----
        {
            int r1 = wm * 16 + rown;
            float cf1 = crow[r1], cf2 = crow[r1 + 8];
#pragma unroll
            for (int ni = 0; ni < 8; ni++) {
                o[ni][0] *= cf1; o[ni][1] *= cf1;
                o[ni][2] *= cf2; o[ni][3] *= cf2;
            }
        }
        const uint32_t vb = kb + 32768;
#pragma unroll
        for (int ks = 0; ks < 4; ks++) {
            const uint32_t bo = ks * 32 + lc16;
            uint32_t pa_h[4], pa_l[4], bvh[4][4], bvl[4][4];
            uint32_t pro = sw128o((uint32_t)((wm * 16 + lr16) * 128 + bo));
            LDMX4(pa_h, sb + ATT_SPH + pro);
            LDMX4(pa_l, sb + ATT_SPL + pro);
            const int vrow = ks * 16 + ((lane >> 3) & 1) * 8 + (lane & 7);
#pragma unroll
            for (int ng = 0; ng < 4; ng++) {
                uint32_t vo = sw128o((uint32_t)(vrow * 128 + ng * 32 + lc16));
                LDMX4T(bvh[ng], vb + wn * 8192 + vo);
                LDMX4T(bvl[ng], vb + 16384 + wn * 8192 + vo);
            }
#pragma unroll
            for (int ni = 0; ni < 8; ni++) {
                const int ng = ni >> 1, sel = (ni & 1) * 2;
                MMA16816(o[ni], pa_h, bvh[ng][sel], bvh[ng][sel + 1]);
            }
#pragma unroll
            for (int ni = 0; ni < 8; ni++) {
                const int ng = ni >> 1, sel = (ni & 1) * 2;
                MMA16816(o[ni], pa_h, bvl[ng][sel], bvl[ng][sel + 1]);
            }
#pragma unroll
            for (int ni = 0; ni < 8; ni++) {
                const int ng = ni >> 1, sel = (ni & 1) * 2;
                MMA16816(o[ni], pa_l, bvh[ng][sel], bvh[ng][sel + 1]);
            }
        }
        __syncthreads();
    }

    // ---- epilogue: normalize + split-bf16 write into ctx (Oh/Ol) ----
    {
        int r1 = wm * 16 + rown;
        float linv1 = 1.f / lrow[r1];
        float linv2 = 1.f / lrow[r1 + 8];
        size_t g1 = ((size_t)(b * TQL + qt * 64 + r1)) * DM + h * HD;
#pragma unroll
        for (int ni = 0; ni < 8; ni++) {
            int col = wn * 64 + ni * 8 + coln;
            __nv_bfloat162 h2, l2;
            split2(o[ni][0] * linv1, o[ni][1] * linv1, h2, l2);
            *(__nv_bfloat162*)(Oh + g1 + col) = h2;
            *(__nv_bfloat162*)(Ol + g1 + col) = l2;
            split2(o[ni][2] * linv2, o[ni][3] * linv2, h2, l2);
            *(__nv_bfloat162*)(Oh + g1 + 8 * DM + col) = h2;
            *(__nv_bfloat162*)(Ol + g1 + 8 * DM + col) = l2;
        }
    }
}

// ============================================================================
extern "C" void kernel_launch(void* const* d_in, const int* in_sizes, int n_in,
                              void* d_out, int out_size)
{
    (void)in_sizes; (void)n_in; (void)out_size;
    const float* query       = (const float*)d_in[0];
    const float* key         = (const float*)d_in[1];
    const float* value       = (const float*)d_in[2];
    const float* cache_key   = (const float*)d_in[3];
    const float* cache_value = (const float*)d_in[4];
    const float* Wq = (const float*)d_in[5];
    const float* bq = (const float*)d_in[6];
    const float* Wk = (const float*)d_in[7];
    const float* bk = (const float*)d_in[8];
    const float* Wv = (const float*)d_in[9];
    const float* bv = (const float*)d_in[10];
    const float* Wo = (const float*)d_in[11];
    const float* bo = (const float*)d_in[12];
    float* out = (float*)d_out;

    __nv_bfloat16 *ah, *al, *wh, *wl, *qh, *ql, *ckh, *ckl, *cvh, *cvl;
    cudaGetSymbolAddress((void**)&ah, g_Ah);
    cudaGetSymbolAddress((void**)&al, g_Al);
    cudaGetSymbolAddress((void**)&wh, g_Wh);
    cudaGetSymbolAddress((void**)&wl, g_Wl);
    cudaGetSymbolAddress((void**)&qh, g_Qh);
    cudaGetSymbolAddress((void**)&ql, g_Ql);
    cudaGetSymbolAddress((void**)&ckh, g_cKh);
    cudaGetSymbolAddress((void**)&ckl, g_cKl);
    cudaGetSymbolAddress((void**)&cvh, g_cVh);
    cudaGetSymbolAddress((void**)&cvl, g_cVl);

    const int GEMM_SMEM = NSTAGE * STAGE_B;  // 196608
    cudaFuncSetAttribute(gemm_mma, cudaFuncAttributeMaxDynamicSharedMemorySize,
                         GEMM_SMEM);
    cudaFuncSetAttribute(attn_mma, cudaFuncAttributeMaxDynamicSharedMemorySize,
                         ATT_SMEMSZ);

    dim3 gg(16, 32);
    // cache K/V split (feeds attention)
    conv_split<<<4096, 256>>>(cache_key, ckh, ckl);
    conv_split<<<4096, 256>>>(cache_value, cvh, cvl);
    // Q projection -> pre-scaled split bf16 Qh/Ql
    conv_split<<<4096, 256>>>(query, ah, al);
    conv_split<<<2048, 256>>>(Wq, wh, wl);
    gemm_mma<<<gg, 256, GEMM_SMEM>>>(ah, al, wh, wl, bq, nullptr, qh, ql, 2);
    // K projection -> new_k (t >= 1024)
    conv_split<<<4096, 256>>>(key, ah, al);
    conv_split<<<2048, 256>>>(Wk, wh, wl);
    gemm_mma<<<gg, 256, GEMM_SMEM>>>(ah, al, wh, wl, bk, out + OFF_K, nullptr, nullptr, 1);
    // V projection -> new_v (t >= 1024)
    conv_split<<<4096, 256>>>(value, ah, al);
    conv_split<<<2048, 256>>>(Wv, wh, wl);
    gemm_mma<<<gg, 256, GEMM_SMEM>>>(ah, al, wh, wl, bv, out + OFF_V, nullptr, nullptr, 1);
    // cache halves of new_k/new_v
    kvcache_copy<<<16384, 256>>>(cache_key, cache_value, out);
    // attention (cache only); writes split ctx into ah/al
    dim3 ga(16, 16, 4);
    attn_mma<<<ga, 256, ATT_SMEMSZ>>>(qh, ql, ckh, ckl, cvh, cvl, ah, al);
    // output projection
    conv_split<<<2048, 256>>>(Wo, wh, wl);
    gemm_mma<<<gg, 256, GEMM_SMEM>>>(ah, al, wh, wl, bo, out, nullptr, nullptr, 0);
}